// round 8
// baseline (speedup 1.0000x reference)
#include <cuda_runtime.h>
#include <math.h>

#define NB 16
#define HW 3136
#define CC 256
#define OH 224
#define OW 224
#define RR 16
#define KS 33
#define NOUT (NB*OH*OW)

__device__ float g_mask56[NB * HW];
__device__ float g_tmp[NOUT];

// ---------------------------------------------------------------------------
// Kernel 1: per-pixel Mahalanobis via tensor cores + symmetry.
// M is exactly symmetric, so only upper-triangle 8x8 tiles (k-tile <= n-tile)
// are read: 528/1024 tiles = 51.6% of the 822 MB stream. Diagonal tiles are
// masked in-register (weight 1 if k<n, 1/2 if k==n, 0 if k>n) and the result
// is doubled: quad[b] = 2 * sum_n V[b,n]*d[b,n], V = D*M_tri.
// Warp w owns n-tiles {w, 15-w, 16+w, 31-w} -> exactly 66 k-tile jobs per
// warp (perfect balance). k-outer loop: A fragment (split tf32 hi/lo) built
// once per k-tile, reused by all active n-tiles. B fragments load straight
// from GMEM in fragment order (each LDG.32 covers full 32B sectors; active
// sectors per row form a contiguous suffix -> no fragmentation).
// Split tf32: x = hi + lo; D*M ~ hi*hi + hi*lo + lo*hi (fp32-class accuracy).
// ---------------------------------------------------------------------------
__global__ __launch_bounds__(256, 3) void maha_kernel(
    const float* __restrict__ x, const float* __restrict__ mean,
    const float* __restrict__ M) {
  const int p = blockIdx.x;
  const int t = threadIdx.x;
  const int wid = t >> 5, lane = t & 31;
  const int tq = lane & 3;    // k-offset within fragment
  const int tr = lane >> 2;   // row/col group index
  __shared__ float sd[CC][NB];   // diff: sd[channel][batch]  (16 KB)
  __shared__ float red[8][NB];

  {
    const float mu = mean[p * CC + t];
    const float* xp = x + (size_t)p * CC + t;
#pragma unroll
    for (int b = 0; b < NB; b++)
      sd[t][b] = xp[(size_t)b * ((size_t)HW * CC)] - mu;
  }
  __syncthreads();

  const float* Mp = M + ((size_t)p << 16);

  // warp's 4 n-tiles (8 cols each); total k-jobs = 66 for every warp
  const int jl[4] = {wid, 15 - wid, 16 + wid, 31 - wid};
  const int jmax = 31 - wid;

  float c0[4], c1[4], c2[4], c3[4];
#pragma unroll
  for (int nt = 0; nt < 4; nt++) { c0[nt] = c1[nt] = c2[nt] = c3[nt] = 0.f; }

  // pointer to M[k=tq][n=tr] for the current k-tile; += 8*CC per k-tile
  const float* Mk = Mp + (size_t)tq * CC + tr;

#pragma unroll 1
  for (int kt = 0; kt <= jmax; kt++, Mk += 8 * CC) {
    const int k0 = kt << 3;
    // ---- A fragment (16x8 of D), split tf32 ----
    const float a0f = sd[k0 + tq][tr];
    const float a1f = sd[k0 + tq][tr + 8];
    const float a2f = sd[k0 + tq + 4][tr];
    const float a3f = sd[k0 + tq + 4][tr + 8];
    unsigned ah0, ah1, ah2, ah3;
    asm("cvt.rna.tf32.f32 %0, %1;" : "=r"(ah0) : "f"(a0f));
    asm("cvt.rna.tf32.f32 %0, %1;" : "=r"(ah1) : "f"(a1f));
    asm("cvt.rna.tf32.f32 %0, %1;" : "=r"(ah2) : "f"(a2f));
    asm("cvt.rna.tf32.f32 %0, %1;" : "=r"(ah3) : "f"(a3f));
    const unsigned al0 = __float_as_uint(a0f - __uint_as_float(ah0));
    const unsigned al1 = __float_as_uint(a1f - __uint_as_float(ah1));
    const unsigned al2 = __float_as_uint(a2f - __uint_as_float(ah2));
    const unsigned al3 = __float_as_uint(a3f - __uint_as_float(ah3));

#pragma unroll
    for (int nt = 0; nt < 4; nt++) {
      const int j = jl[nt];
      if (j < kt) continue;          // below diagonal: tile not needed
      // ---- B fragment (8x8 of M): rows k0+tq / k0+tq+4, col j*8+tr ----
      float b0f = Mk[j * 8];
      float b1f = Mk[j * 8 + 4 * CC];
      if (j == kt) {
        // triangular weight within the diagonal tile
        b0f = (tq < tr) ? b0f : (tq == tr) ? 0.5f * b0f : 0.f;
        const int r1 = tq + 4;
        b1f = (r1 < tr) ? b1f : (r1 == tr) ? 0.5f * b1f : 0.f;
      }
      unsigned bh0, bh1;
      asm("cvt.rna.tf32.f32 %0, %1;" : "=r"(bh0) : "f"(b0f));
      asm("cvt.rna.tf32.f32 %0, %1;" : "=r"(bh1) : "f"(b1f));
      const unsigned bl0 = __float_as_uint(b0f - __uint_as_float(bh0));
      const unsigned bl1 = __float_as_uint(b1f - __uint_as_float(bh1));

      asm("mma.sync.aligned.m16n8k8.row.col.f32.tf32.tf32.f32 "
          "{%0,%1,%2,%3}, {%4,%5,%6,%7}, {%8,%9}, {%0,%1,%2,%3};"
          : "+f"(c0[nt]), "+f"(c1[nt]), "+f"(c2[nt]), "+f"(c3[nt])
          : "r"(ah0), "r"(ah1), "r"(ah2), "r"(ah3), "r"(bh0), "r"(bh1));
      asm("mma.sync.aligned.m16n8k8.row.col.f32.tf32.tf32.f32 "
          "{%0,%1,%2,%3}, {%4,%5,%6,%7}, {%8,%9}, {%0,%1,%2,%3};"
          : "+f"(c0[nt]), "+f"(c1[nt]), "+f"(c2[nt]), "+f"(c3[nt])
          : "r"(ah0), "r"(ah1), "r"(ah2), "r"(ah3), "r"(bl0), "r"(bl1));
      asm("mma.sync.aligned.m16n8k8.row.col.f32.tf32.tf32.f32 "
          "{%0,%1,%2,%3}, {%4,%5,%6,%7}, {%8,%9}, {%0,%1,%2,%3};"
          : "+f"(c0[nt]), "+f"(c1[nt]), "+f"(c2[nt]), "+f"(c3[nt])
          : "r"(al0), "r"(al1), "r"(al2), "r"(al3), "r"(bh0), "r"(bh1));
    }
  }

  // ---- epilogue: q[b] += V[b,n] * d[b,n]; quad = 2 * total ----
  // C frag: c0:(tr, 2tq) c1:(tr, 2tq+1) c2:(tr+8, 2tq) c3:(tr+8, 2tq+1)
  float q0 = 0.f, q1 = 0.f;
#pragma unroll
  for (int nt = 0; nt < 4; nt++) {
    const int n = jl[nt] * 8 + tq * 2;
    q0 += c0[nt] * sd[n][tr]     + c1[nt] * sd[n + 1][tr];
    q1 += c2[nt] * sd[n][tr + 8] + c3[nt] * sd[n + 1][tr + 8];
  }
  q0 += __shfl_xor_sync(0xffffffffu, q0, 1);
  q0 += __shfl_xor_sync(0xffffffffu, q0, 2);
  q1 += __shfl_xor_sync(0xffffffffu, q1, 1);
  q1 += __shfl_xor_sync(0xffffffffu, q1, 2);
  if (tq == 0) {
    red[wid][tr] = q0;
    red[wid][tr + 8] = q1;
  }
  __syncthreads();
  if (t < NB) {
    float s = 0.f;
#pragma unroll
    for (int w = 0; w < 8; w++) s += red[w][t];
    g_mask56[t * HW + p] = sqrtf(fmaxf(2.0f * s, 0.f));
  }
}

__device__ __forceinline__ int reflect101(int i) {
  if (i < 0) i = -i;
  if (i > 223) i = 446 - i;
  return i;
}

__device__ __forceinline__ void load_weights(float* w, float* inv) {
  const int tid = threadIdx.x;
  if (tid < KS) {
    const float d = (float)(tid - RR);
    w[tid] = expf(-(d * d) / 32.0f);
  }
  __syncthreads();
  if (tid == 0) {
    float s = 0.f;
    for (int j = 0; j < KS; j++) s += w[j];
    *inv = 1.0f / s;
  }
}

// ---------------------------------------------------------------------------
// Kernel 2: FUSED bilinear resize (56->224) + vertical blur; zeroes scores.
// ---------------------------------------------------------------------------
__global__ __launch_bounds__(256) void blur_v_kernel(float* __restrict__ score) {
  __shared__ float s[OH + 32][17];
  __shared__ float w[KS];
  __shared__ float inv;
  load_weights(w, &inv);
  const int tid = threadIdx.x;
  if (blockIdx.x == 0 && tid < NB) score[tid] = 0.0f;
  const int b = blockIdx.x / 14;
  const int xt = (blockIdx.x % 14) * 16;
  const float* mp = g_mask56 + b * HW;
#pragma unroll
  for (int li = tid; li < (OH + 32) * 16; li += 256) {
    const int r = li >> 4, c = li & 15;
    const int gy = reflect101(r - RR);
    const int gx = xt + c;
    const float fy = (gy + 0.5f) * 0.25f - 0.5f;
    const float fx = (gx + 0.5f) * 0.25f - 0.5f;
    const int y0 = (int)floorf(fy);
    const int x0 = (int)floorf(fx);
    const float wy = fy - (float)y0;
    const float wx = fx - (float)x0;
    const int y0c = min(max(y0, 0), 55), y1c = min(max(y0 + 1, 0), 55);
    const int x0c = min(max(x0, 0), 55), x1c = min(max(x0 + 1, 0), 55);
    const float v00 = mp[y0c * 56 + x0c];
    const float v01 = mp[y0c * 56 + x1c];
    const float v10 = mp[y1c * 56 + x0c];
    const float v11 = mp[y1c * 56 + x1c];
    s[r][c] = (1.f - wy) * ((1.f - wx) * v00 + wx * v01) +
              wy * ((1.f - wx) * v10 + wx * v11);
  }
  __syncthreads();
  float* dst = g_tmp + b * OH * OW + xt;
  const int c = tid & 15;
  for (int y = tid >> 4; y < OH; y += 16) {
    float sum = 0.f;
#pragma unroll
    for (int j = 0; j < KS; j++) sum += w[j] * s[y + j][c];
    dst[y * OW + c] = sum * inv;
  }
}

// ---------------------------------------------------------------------------
// Kernel 3: horizontal blur + per-batch max.
// ---------------------------------------------------------------------------
__global__ __launch_bounds__(256) void blur_h_kernel(float* __restrict__ out_mask,
                                                     float* __restrict__ score) {
  __shared__ float s[8][256];
  __shared__ float w[KS];
  __shared__ float inv;
  __shared__ float smx[8];
  load_weights(w, &inv);
  const int tid = threadIdx.x;
  const int b = blockIdx.x / 28;
  const int yt = (blockIdx.x % 28) * 8;
  const float* src = g_tmp + (b * OH + yt) * OW;
#pragma unroll
  for (int li = tid; li < 8 * 256; li += 256) {
    const int r = li >> 8, c = li & 255;
    const int gx = reflect101(c - RR);
    s[r][c] = src[r * OW + gx];
  }
  __syncthreads();
  float* dst = out_mask + (b * OH + yt) * OW;
  const int lane = tid & 31;
  const int r = tid >> 5;
  float mx = 0.f;
#pragma unroll
  for (int x0 = 0; x0 < OW; x0 += 32) {
    const int x = x0 + lane;
    float sum = 0.f;
#pragma unroll
    for (int j = 0; j < KS; j++) sum += w[j] * s[r][x + j];
    sum *= inv;
    dst[r * OW + x] = sum;
    mx = fmaxf(mx, sum);
  }
#pragma unroll
  for (int off = 16; off > 0; off >>= 1)
    mx = fmaxf(mx, __shfl_down_sync(0xffffffffu, mx, off));
  if (lane == 0) smx[r] = mx;
  __syncthreads();
  if (tid == 0) {
    float m2 = smx[0];
#pragma unroll
    for (int k = 1; k < 8; k++) m2 = fmaxf(m2, smx[k]);
    atomicMax((int*)&score[b], __float_as_int(m2));
  }
}

extern "C" void kernel_launch(void* const* d_in, const int* in_sizes, int n_in,
                              void* d_out, int out_size) {
  const float* inputs = (const float*)d_in[0];    // [16,56,56,256]
  const float* mean = (const float*)d_in[1];      // [3136,256]
  const float* cvar_inv = (const float*)d_in[2];  // [3136,256,256]
  float* out = (float*)d_out;
  float* score = out;          // [16,1]
  float* mask = out + NB;      // [16,224,224,1]

  maha_kernel<<<HW, 256>>>(inputs, mean, cvar_inv);
  blur_v_kernel<<<16 * 14, 256>>>(score);
  blur_h_kernel<<<16 * 28, 256>>>(mask, score);
}

// round 9
// speedup vs baseline: 1.1294x; 1.1294x over previous
#include <cuda_runtime.h>
#include <math.h>

#define NB 16
#define HW 3136
#define CC 256
#define OH 224
#define OW 224
#define RR 16
#define KS 33
#define NOUT (NB*OH*OW)

__device__ float g_mask56[NB * HW];
__device__ float g_tmp[NOUT];

// ---------------------------------------------------------------------------
// Kernel 1: per-pixel Mahalanobis via tensor cores (tf32 split), full-matrix
// streaming (R7 skeleton: 5.26 TB/s) + register double-buffering of the B
// stream + occupancy 4 to close the remaining DRAM headroom.
// quad[b] = sum_c V[b,c]*d[b,c], V = D*M (16x256x256 GEMM per pixel).
// Warp w owns N-cols [32w,32w+32) as 4 m16n8k8 n-tiles; k loop 8 rows/step.
// B fragments load straight from GMEM in fragment order; the 8 floats for
// step k+8 are issued BEFORE step k's cvt/MMA work, so every warp keeps 8
// LDGs in flight through each compute phase.
// Split tf32: x = hi + lo; D*M ~ hi*hi + hi*lo + lo*hi (fp32-class accuracy).
// ---------------------------------------------------------------------------
__global__ __launch_bounds__(256, 4) void maha_kernel(
    const float* __restrict__ x, const float* __restrict__ mean,
    const float* __restrict__ M) {
  const int p = blockIdx.x;
  const int t = threadIdx.x;
  const int wid = t >> 5, lane = t & 31;
  const int tq = lane & 3;    // k-offset within fragment
  const int tr = lane >> 2;   // row/col group index
  __shared__ float sd[CC][NB];   // diff: sd[channel][batch]  (16 KB)
  __shared__ float red[8][NB];

  {
    const float mu = mean[p * CC + t];
    const float* xp = x + (size_t)p * CC + t;
#pragma unroll
    for (int b = 0; b < NB; b++)
      sd[t][b] = xp[(size_t)b * ((size_t)HW * CC)] - mu;
  }
  __syncthreads();

  const float* Mp = M + ((size_t)p << 16);
  const int n0 = wid << 5;

  float c0[4], c1[4], c2[4], c3[4];
#pragma unroll
  for (int nt = 0; nt < 4; nt++) { c0[nt] = c1[nt] = c2[nt] = c3[nt] = 0.f; }

  // B pointer for current k-step: M[k0+tq][n0+tr]
  const float* Mk = Mp + (size_t)tq * CC + n0 + tr;

  // prologue: load B floats for k0 = 0 (4 n-tiles x 2 rows)
  float bf[8];
#pragma unroll
  for (int nt = 0; nt < 4; nt++) {
    bf[2 * nt] = Mk[nt * 8];
    bf[2 * nt + 1] = Mk[nt * 8 + 4 * CC];
  }

#pragma unroll 1
  for (int k0 = 0; k0 < CC; k0 += 8) {
    // ---- prefetch next k-step's B floats (clamped on last iter) ----
    const float* Mn = (k0 + 8 < CC) ? (Mk + 8 * CC) : Mk;
    float bn[8];
#pragma unroll
    for (int nt = 0; nt < 4; nt++) {
      bn[2 * nt] = Mn[nt * 8];
      bn[2 * nt + 1] = Mn[nt * 8 + 4 * CC];
    }
    Mk = Mn;

    // ---- A fragment (16x8 of D), split tf32 ----
    const float a0f = sd[k0 + tq][tr];
    const float a1f = sd[k0 + tq][tr + 8];
    const float a2f = sd[k0 + tq + 4][tr];
    const float a3f = sd[k0 + tq + 4][tr + 8];
    unsigned ah0, ah1, ah2, ah3;
    asm("cvt.rna.tf32.f32 %0, %1;" : "=r"(ah0) : "f"(a0f));
    asm("cvt.rna.tf32.f32 %0, %1;" : "=r"(ah1) : "f"(a1f));
    asm("cvt.rna.tf32.f32 %0, %1;" : "=r"(ah2) : "f"(a2f));
    asm("cvt.rna.tf32.f32 %0, %1;" : "=r"(ah3) : "f"(a3f));
    const unsigned al0 = __float_as_uint(a0f - __uint_as_float(ah0));
    const unsigned al1 = __float_as_uint(a1f - __uint_as_float(ah1));
    const unsigned al2 = __float_as_uint(a2f - __uint_as_float(ah2));
    const unsigned al3 = __float_as_uint(a3f - __uint_as_float(ah3));

#pragma unroll
    for (int nt = 0; nt < 4; nt++) {
      const float b0f = bf[2 * nt];
      const float b1f = bf[2 * nt + 1];
      unsigned bh0, bh1;
      asm("cvt.rna.tf32.f32 %0, %1;" : "=r"(bh0) : "f"(b0f));
      asm("cvt.rna.tf32.f32 %0, %1;" : "=r"(bh1) : "f"(b1f));
      const unsigned bl0 = __float_as_uint(b0f - __uint_as_float(bh0));
      const unsigned bl1 = __float_as_uint(b1f - __uint_as_float(bh1));

      asm("mma.sync.aligned.m16n8k8.row.col.f32.tf32.tf32.f32 "
          "{%0,%1,%2,%3}, {%4,%5,%6,%7}, {%8,%9}, {%0,%1,%2,%3};"
          : "+f"(c0[nt]), "+f"(c1[nt]), "+f"(c2[nt]), "+f"(c3[nt])
          : "r"(ah0), "r"(ah1), "r"(ah2), "r"(ah3), "r"(bh0), "r"(bh1));
      asm("mma.sync.aligned.m16n8k8.row.col.f32.tf32.tf32.f32 "
          "{%0,%1,%2,%3}, {%4,%5,%6,%7}, {%8,%9}, {%0,%1,%2,%3};"
          : "+f"(c0[nt]), "+f"(c1[nt]), "+f"(c2[nt]), "+f"(c3[nt])
          : "r"(ah0), "r"(ah1), "r"(ah2), "r"(ah3), "r"(bl0), "r"(bl1));
      asm("mma.sync.aligned.m16n8k8.row.col.f32.tf32.tf32.f32 "
          "{%0,%1,%2,%3}, {%4,%5,%6,%7}, {%8,%9}, {%0,%1,%2,%3};"
          : "+f"(c0[nt]), "+f"(c1[nt]), "+f"(c2[nt]), "+f"(c3[nt])
          : "r"(al0), "r"(al1), "r"(al2), "r"(al3), "r"(bh0), "r"(bh1));
    }

#pragma unroll
    for (int u = 0; u < 8; u++) bf[u] = bn[u];
  }

  // ---- epilogue: q[b] += V[b,n] * d[b,n] over this warp's 32 cols ----
  // C frag: c0:(tr, 2tq) c1:(tr, 2tq+1) c2:(tr+8, 2tq) c3:(tr+8, 2tq+1)
  float q0 = 0.f, q1 = 0.f;
#pragma unroll
  for (int nt = 0; nt < 4; nt++) {
    const int n = n0 + nt * 8 + tq * 2;
    q0 += c0[nt] * sd[n][tr]     + c1[nt] * sd[n + 1][tr];
    q1 += c2[nt] * sd[n][tr + 8] + c3[nt] * sd[n + 1][tr + 8];
  }
  q0 += __shfl_xor_sync(0xffffffffu, q0, 1);
  q0 += __shfl_xor_sync(0xffffffffu, q0, 2);
  q1 += __shfl_xor_sync(0xffffffffu, q1, 1);
  q1 += __shfl_xor_sync(0xffffffffu, q1, 2);
  if (tq == 0) {
    red[wid][tr] = q0;
    red[wid][tr + 8] = q1;
  }
  __syncthreads();
  if (t < NB) {
    float s = 0.f;
#pragma unroll
    for (int w = 0; w < 8; w++) s += red[w][t];
    g_mask56[t * HW + p] = sqrtf(fmaxf(s, 0.f));
  }
}

__device__ __forceinline__ int reflect101(int i) {
  if (i < 0) i = -i;
  if (i > 223) i = 446 - i;
  return i;
}

__device__ __forceinline__ void load_weights(float* w, float* inv) {
  const int tid = threadIdx.x;
  if (tid < KS) {
    const float d = (float)(tid - RR);
    w[tid] = expf(-(d * d) / 32.0f);
  }
  __syncthreads();
  if (tid == 0) {
    float s = 0.f;
    for (int j = 0; j < KS; j++) s += w[j];
    *inv = 1.0f / s;
  }
}

// ---------------------------------------------------------------------------
// Kernel 2: FUSED bilinear resize (56->224) + vertical blur; zeroes scores.
// ---------------------------------------------------------------------------
__global__ __launch_bounds__(256) void blur_v_kernel(float* __restrict__ score) {
  __shared__ float s[OH + 32][17];
  __shared__ float w[KS];
  __shared__ float inv;
  load_weights(w, &inv);
  const int tid = threadIdx.x;
  if (blockIdx.x == 0 && tid < NB) score[tid] = 0.0f;
  const int b = blockIdx.x / 14;
  const int xt = (blockIdx.x % 14) * 16;
  const float* mp = g_mask56 + b * HW;
#pragma unroll
  for (int li = tid; li < (OH + 32) * 16; li += 256) {
    const int r = li >> 4, c = li & 15;
    const int gy = reflect101(r - RR);
    const int gx = xt + c;
    const float fy = (gy + 0.5f) * 0.25f - 0.5f;
    const float fx = (gx + 0.5f) * 0.25f - 0.5f;
    const int y0 = (int)floorf(fy);
    const int x0 = (int)floorf(fx);
    const float wy = fy - (float)y0;
    const float wx = fx - (float)x0;
    const int y0c = min(max(y0, 0), 55), y1c = min(max(y0 + 1, 0), 55);
    const int x0c = min(max(x0, 0), 55), x1c = min(max(x0 + 1, 0), 55);
    const float v00 = mp[y0c * 56 + x0c];
    const float v01 = mp[y0c * 56 + x1c];
    const float v10 = mp[y1c * 56 + x0c];
    const float v11 = mp[y1c * 56 + x1c];
    s[r][c] = (1.f - wy) * ((1.f - wx) * v00 + wx * v01) +
              wy * ((1.f - wx) * v10 + wx * v11);
  }
  __syncthreads();
  float* dst = g_tmp + b * OH * OW + xt;
  const int c = tid & 15;
  for (int y = tid >> 4; y < OH; y += 16) {
    float sum = 0.f;
#pragma unroll
    for (int j = 0; j < KS; j++) sum += w[j] * s[y + j][c];
    dst[y * OW + c] = sum * inv;
  }
}

// ---------------------------------------------------------------------------
// Kernel 3: horizontal blur + per-batch max.
// ---------------------------------------------------------------------------
__global__ __launch_bounds__(256) void blur_h_kernel(float* __restrict__ out_mask,
                                                     float* __restrict__ score) {
  __shared__ float s[8][256];
  __shared__ float w[KS];
  __shared__ float inv;
  __shared__ float smx[8];
  load_weights(w, &inv);
  const int tid = threadIdx.x;
  const int b = blockIdx.x / 28;
  const int yt = (blockIdx.x % 28) * 8;
  const float* src = g_tmp + (b * OH + yt) * OW;
#pragma unroll
  for (int li = tid; li < 8 * 256; li += 256) {
    const int r = li >> 8, c = li & 255;
    const int gx = reflect101(c - RR);
    s[r][c] = src[r * OW + gx];
  }
  __syncthreads();
  float* dst = out_mask + (b * OH + yt) * OW;
  const int lane = tid & 31;
  const int r = tid >> 5;
  float mx = 0.f;
#pragma unroll
  for (int x0 = 0; x0 < OW; x0 += 32) {
    const int x = x0 + lane;
    float sum = 0.f;
#pragma unroll
    for (int j = 0; j < KS; j++) sum += w[j] * s[r][x + j];
    sum *= inv;
    dst[r * OW + x] = sum;
    mx = fmaxf(mx, sum);
  }
#pragma unroll
  for (int off = 16; off > 0; off >>= 1)
    mx = fmaxf(mx, __shfl_down_sync(0xffffffffu, mx, off));
  if (lane == 0) smx[r] = mx;
  __syncthreads();
  if (tid == 0) {
    float m2 = smx[0];
#pragma unroll
    for (int k = 1; k < 8; k++) m2 = fmaxf(m2, smx[k]);
    atomicMax((int*)&score[b], __float_as_int(m2));
  }
}

extern "C" void kernel_launch(void* const* d_in, const int* in_sizes, int n_in,
                              void* d_out, int out_size) {
  const float* inputs = (const float*)d_in[0];    // [16,56,56,256]
  const float* mean = (const float*)d_in[1];      // [3136,256]
  const float* cvar_inv = (const float*)d_in[2];  // [3136,256,256]
  float* out = (float*)d_out;
  float* score = out;          // [16,1]
  float* mask = out + NB;      // [16,224,224,1]

  maha_kernel<<<HW, 256>>>(inputs, mean, cvar_inv);
  blur_v_kernel<<<16 * 14, 256>>>(score);
  blur_h_kernel<<<16 * 28, 256>>>(mask, score);
}

// round 10
// speedup vs baseline: 1.6743x; 1.4824x over previous
#include <cuda_runtime.h>
#include <math.h>

#define NB 16
#define HW 3136
#define CC 256
#define OH 224
#define OW 224
#define RR 16
#define KS 33
#define NOUT (NB*OH*OW)

__device__ float g_mask56[NB * HW];
__device__ float g_tmp[NOUT];

// ---------------------------------------------------------------------------
// One k-step (8 rows) of the per-pixel GEMM: A fragment from sd (split tf32),
// B floats already in registers (bf[8]); 3 MMAs per n-tile (hi*hi, hi*lo,
// lo*hi) for fp32-class accuracy.
// ---------------------------------------------------------------------------
__device__ __forceinline__ void mma_step(
    const float (*sd)[NB], int k0, int tq, int tr, const float* bf,
    float* c0, float* c1, float* c2, float* c3) {
  const float a0f = sd[k0 + tq][tr];
  const float a1f = sd[k0 + tq][tr + 8];
  const float a2f = sd[k0 + tq + 4][tr];
  const float a3f = sd[k0 + tq + 4][tr + 8];
  unsigned ah0, ah1, ah2, ah3;
  asm("cvt.rna.tf32.f32 %0, %1;" : "=r"(ah0) : "f"(a0f));
  asm("cvt.rna.tf32.f32 %0, %1;" : "=r"(ah1) : "f"(a1f));
  asm("cvt.rna.tf32.f32 %0, %1;" : "=r"(ah2) : "f"(a2f));
  asm("cvt.rna.tf32.f32 %0, %1;" : "=r"(ah3) : "f"(a3f));
  const unsigned al0 = __float_as_uint(a0f - __uint_as_float(ah0));
  const unsigned al1 = __float_as_uint(a1f - __uint_as_float(ah1));
  const unsigned al2 = __float_as_uint(a2f - __uint_as_float(ah2));
  const unsigned al3 = __float_as_uint(a3f - __uint_as_float(ah3));

#pragma unroll
  for (int nt = 0; nt < 4; nt++) {
    const float b0f = bf[2 * nt];
    const float b1f = bf[2 * nt + 1];
    unsigned bh0, bh1;
    asm("cvt.rna.tf32.f32 %0, %1;" : "=r"(bh0) : "f"(b0f));
    asm("cvt.rna.tf32.f32 %0, %1;" : "=r"(bh1) : "f"(b1f));
    const unsigned bl0 = __float_as_uint(b0f - __uint_as_float(bh0));
    const unsigned bl1 = __float_as_uint(b1f - __uint_as_float(bh1));

    asm("mma.sync.aligned.m16n8k8.row.col.f32.tf32.tf32.f32 "
        "{%0,%1,%2,%3}, {%4,%5,%6,%7}, {%8,%9}, {%0,%1,%2,%3};"
        : "+f"(c0[nt]), "+f"(c1[nt]), "+f"(c2[nt]), "+f"(c3[nt])
        : "r"(ah0), "r"(ah1), "r"(ah2), "r"(ah3), "r"(bh0), "r"(bh1));
    asm("mma.sync.aligned.m16n8k8.row.col.f32.tf32.tf32.f32 "
        "{%0,%1,%2,%3}, {%4,%5,%6,%7}, {%8,%9}, {%0,%1,%2,%3};"
        : "+f"(c0[nt]), "+f"(c1[nt]), "+f"(c2[nt]), "+f"(c3[nt])
        : "r"(ah0), "r"(ah1), "r"(ah2), "r"(ah3), "r"(bl0), "r"(bl1));
    asm("mma.sync.aligned.m16n8k8.row.col.f32.tf32.tf32.f32 "
        "{%0,%1,%2,%3}, {%4,%5,%6,%7}, {%8,%9}, {%0,%1,%2,%3};"
        : "+f"(c0[nt]), "+f"(c1[nt]), "+f"(c2[nt]), "+f"(c3[nt])
        : "r"(al0), "r"(al1), "r"(al2), "r"(al3), "r"(bh0), "r"(bh1));
  }
}

// ---------------------------------------------------------------------------
// Kernel 1: per-pixel Mahalanobis via tensor cores (tf32 split), full-matrix
// streaming. R7 skeleton (occ 3, no spills) + TWO-PHASE register double
// buffering with zero copies: even phase computes from bufA while bufB loads,
// odd phase the reverse. Each warp keeps 8 LDGs in flight through every
// compute phase (prefetch distance = one full phase).
// ---------------------------------------------------------------------------
__global__ __launch_bounds__(256, 3) void maha_kernel(
    const float* __restrict__ x, const float* __restrict__ mean,
    const float* __restrict__ M) {
  const int p = blockIdx.x;
  const int t = threadIdx.x;
  const int wid = t >> 5, lane = t & 31;
  const int tq = lane & 3;    // k-offset within fragment
  const int tr = lane >> 2;   // row/col group index
  __shared__ float sd[CC][NB];   // diff: sd[channel][batch]  (16 KB)
  __shared__ float red[8][NB];

  {
    const float mu = mean[p * CC + t];
    const float* xp = x + (size_t)p * CC + t;
#pragma unroll
    for (int b = 0; b < NB; b++)
      sd[t][b] = xp[(size_t)b * ((size_t)HW * CC)] - mu;
  }
  __syncthreads();

  const float* Mp = M + ((size_t)p << 16);
  const int n0 = wid << 5;

  float c0[4], c1[4], c2[4], c3[4];
#pragma unroll
  for (int nt = 0; nt < 4; nt++) { c0[nt] = c1[nt] = c2[nt] = c3[nt] = 0.f; }

  // load pointer: M[k+tq][n0+tr]; advance 8*CC per k-step
  const float* Ml = Mp + (size_t)tq * CC + n0 + tr;

  float bufA[8], bufB[8];
#pragma unroll
  for (int nt = 0; nt < 4; nt++) {       // k-step 0
    bufA[2 * nt] = Ml[nt * 8];
    bufA[2 * nt + 1] = Ml[nt * 8 + 4 * CC];
  }

#pragma unroll 1
  for (int k0 = 0; k0 < CC; k0 += 16) {
    Ml += 8 * CC;                        // k-step k0+8 (always < 256: max 248)
#pragma unroll
    for (int nt = 0; nt < 4; nt++) {
      bufB[2 * nt] = Ml[nt * 8];
      bufB[2 * nt + 1] = Ml[nt * 8 + 4 * CC];
    }
    mma_step(sd, k0, tq, tr, bufA, c0, c1, c2, c3);

    if (k0 + 16 < CC) Ml += 8 * CC;      // k-step k0+16 (tail: harmless reload)
#pragma unroll
    for (int nt = 0; nt < 4; nt++) {
      bufA[2 * nt] = Ml[nt * 8];
      bufA[2 * nt + 1] = Ml[nt * 8 + 4 * CC];
    }
    mma_step(sd, k0 + 8, tq, tr, bufB, c0, c1, c2, c3);
  }

  // ---- epilogue: q[b] += V[b,n] * d[b,n] over this warp's 32 cols ----
  // C frag: c0:(tr, 2tq) c1:(tr, 2tq+1) c2:(tr+8, 2tq) c3:(tr+8, 2tq+1)
  float q0 = 0.f, q1 = 0.f;
#pragma unroll
  for (int nt = 0; nt < 4; nt++) {
    const int n = n0 + nt * 8 + tq * 2;
    q0 += c0[nt] * sd[n][tr]     + c1[nt] * sd[n + 1][tr];
    q1 += c2[nt] * sd[n][tr + 8] + c3[nt] * sd[n + 1][tr + 8];
  }
  q0 += __shfl_xor_sync(0xffffffffu, q0, 1);
  q0 += __shfl_xor_sync(0xffffffffu, q0, 2);
  q1 += __shfl_xor_sync(0xffffffffu, q1, 1);
  q1 += __shfl_xor_sync(0xffffffffu, q1, 2);
  if (tq == 0) {
    red[wid][tr] = q0;
    red[wid][tr + 8] = q1;
  }
  __syncthreads();
  if (t < NB) {
    float s = 0.f;
#pragma unroll
    for (int w = 0; w < 8; w++) s += red[w][t];
    g_mask56[t * HW + p] = sqrtf(fmaxf(s, 0.f));
  }
}

__device__ __forceinline__ int reflect101(int i) {
  if (i < 0) i = -i;
  if (i > 223) i = 446 - i;
  return i;
}

__device__ __forceinline__ void load_weights(float* w, float* inv) {
  const int tid = threadIdx.x;
  if (tid < KS) {
    const float d = (float)(tid - RR);
    w[tid] = expf(-(d * d) / 32.0f);
  }
  __syncthreads();
  if (tid == 0) {
    float s = 0.f;
    for (int j = 0; j < KS; j++) s += w[j];
    *inv = 1.0f / s;
  }
}

// ---------------------------------------------------------------------------
// Kernel 2: FUSED bilinear resize (56->224) + vertical blur; zeroes scores.
// ---------------------------------------------------------------------------
__global__ __launch_bounds__(256) void blur_v_kernel(float* __restrict__ score) {
  __shared__ float s[OH + 32][17];
  __shared__ float w[KS];
  __shared__ float inv;
  load_weights(w, &inv);
  const int tid = threadIdx.x;
  if (blockIdx.x == 0 && tid < NB) score[tid] = 0.0f;
  const int b = blockIdx.x / 14;
  const int xt = (blockIdx.x % 14) * 16;
  const float* mp = g_mask56 + b * HW;
#pragma unroll
  for (int li = tid; li < (OH + 32) * 16; li += 256) {
    const int r = li >> 4, c = li & 15;
    const int gy = reflect101(r - RR);
    const int gx = xt + c;
    const float fy = (gy + 0.5f) * 0.25f - 0.5f;
    const float fx = (gx + 0.5f) * 0.25f - 0.5f;
    const int y0 = (int)floorf(fy);
    const int x0 = (int)floorf(fx);
    const float wy = fy - (float)y0;
    const float wx = fx - (float)x0;
    const int y0c = min(max(y0, 0), 55), y1c = min(max(y0 + 1, 0), 55);
    const int x0c = min(max(x0, 0), 55), x1c = min(max(x0 + 1, 0), 55);
    const float v00 = mp[y0c * 56 + x0c];
    const float v01 = mp[y0c * 56 + x1c];
    const float v10 = mp[y1c * 56 + x0c];
    const float v11 = mp[y1c * 56 + x1c];
    s[r][c] = (1.f - wy) * ((1.f - wx) * v00 + wx * v01) +
              wy * ((1.f - wx) * v10 + wx * v11);
  }
  __syncthreads();
  float* dst = g_tmp + b * OH * OW + xt;
  const int c = tid & 15;
  for (int y = tid >> 4; y < OH; y += 16) {
    float sum = 0.f;
#pragma unroll
    for (int j = 0; j < KS; j++) sum += w[j] * s[y + j][c];
    dst[y * OW + c] = sum * inv;
  }
}

// ---------------------------------------------------------------------------
// Kernel 3: horizontal blur + per-batch max.
// ---------------------------------------------------------------------------
__global__ __launch_bounds__(256) void blur_h_kernel(float* __restrict__ out_mask,
                                                     float* __restrict__ score) {
  __shared__ float s[8][256];
  __shared__ float w[KS];
  __shared__ float inv;
  __shared__ float smx[8];
  load_weights(w, &inv);
  const int tid = threadIdx.x;
  const int b = blockIdx.x / 28;
  const int yt = (blockIdx.x % 28) * 8;
  const float* src = g_tmp + (b * OH + yt) * OW;
#pragma unroll
  for (int li = tid; li < 8 * 256; li += 256) {
    const int r = li >> 8, c = li & 255;
    const int gx = reflect101(c - RR);
    s[r][c] = src[r * OW + gx];
  }
  __syncthreads();
  float* dst = out_mask + (b * OH + yt) * OW;
  const int lane = tid & 31;
  const int r = tid >> 5;
  float mx = 0.f;
#pragma unroll
  for (int x0 = 0; x0 < OW; x0 += 32) {
    const int x = x0 + lane;
    float sum = 0.f;
#pragma unroll
    for (int j = 0; j < KS; j++) sum += w[j] * s[r][x + j];
    sum *= inv;
    dst[r * OW + x] = sum;
    mx = fmaxf(mx, sum);
  }
#pragma unroll
  for (int off = 16; off > 0; off >>= 1)
    mx = fmaxf(mx, __shfl_down_sync(0xffffffffu, mx, off));
  if (lane == 0) smx[r] = mx;
  __syncthreads();
  if (tid == 0) {
    float m2 = smx[0];
#pragma unroll
    for (int k = 1; k < 8; k++) m2 = fmaxf(m2, smx[k]);
    atomicMax((int*)&score[b], __float_as_int(m2));
  }
}

extern "C" void kernel_launch(void* const* d_in, const int* in_sizes, int n_in,
                              void* d_out, int out_size) {
  const float* inputs = (const float*)d_in[0];    // [16,56,56,256]
  const float* mean = (const float*)d_in[1];      // [3136,256]
  const float* cvar_inv = (const float*)d_in[2];  // [3136,256,256]
  float* out = (float*)d_out;
  float* score = out;          // [16,1]
  float* mask = out + NB;      // [16,224,224,1]

  maha_kernel<<<HW, 256>>>(inputs, mean, cvar_inv);
  blur_v_kernel<<<16 * 14, 256>>>(score);
  blur_h_kernel<<<16 * 28, 256>>>(mask, score);
}

// round 11
// speedup vs baseline: 1.7295x; 1.0330x over previous
#include <cuda_runtime.h>
#include <math.h>

#define NB 16
#define HW 3136
#define CC 256
#define OH 224
#define OW 224
#define RR 16
#define KS 33
#define NOUT (NB*OH*OW)

__device__ float g_mask56[NB * HW];
__device__ float g_tmp[NOUT];

// ---------------------------------------------------------------------------
// One k-step (8 rows) of the per-pixel GEMM, plain tf32 (no split).
// Error analysis: products ~0.09 abs, tf32 rounding sigma 2.8e-4 rel,
// 65k products -> quad rel err ~2e-5 << 1e-3 gate (and sqrt halves it).
// ---------------------------------------------------------------------------
__device__ __forceinline__ void mma_step(
    const float (*sd)[NB], int k0, int tq, int tr, const float* bf,
    float* c0, float* c1, float* c2, float* c3) {
  unsigned ah0, ah1, ah2, ah3;
  asm("cvt.rna.tf32.f32 %0, %1;" : "=r"(ah0) : "f"(sd[k0 + tq][tr]));
  asm("cvt.rna.tf32.f32 %0, %1;" : "=r"(ah1) : "f"(sd[k0 + tq][tr + 8]));
  asm("cvt.rna.tf32.f32 %0, %1;" : "=r"(ah2) : "f"(sd[k0 + tq + 4][tr]));
  asm("cvt.rna.tf32.f32 %0, %1;" : "=r"(ah3) : "f"(sd[k0 + tq + 4][tr + 8]));

#pragma unroll
  for (int nt = 0; nt < 4; nt++) {
    unsigned bh0, bh1;
    asm("cvt.rna.tf32.f32 %0, %1;" : "=r"(bh0) : "f"(bf[2 * nt]));
    asm("cvt.rna.tf32.f32 %0, %1;" : "=r"(bh1) : "f"(bf[2 * nt + 1]));
    asm("mma.sync.aligned.m16n8k8.row.col.f32.tf32.tf32.f32 "
        "{%0,%1,%2,%3}, {%4,%5,%6,%7}, {%8,%9}, {%0,%1,%2,%3};"
        : "+f"(c0[nt]), "+f"(c1[nt]), "+f"(c2[nt]), "+f"(c3[nt])
        : "r"(ah0), "r"(ah1), "r"(ah2), "r"(ah3), "r"(bh0), "r"(bh1));
  }
}

// ---------------------------------------------------------------------------
// Kernel 1: per-pixel Mahalanobis via tensor cores (plain tf32), full-matrix
// streaming, two-phase register double buffering (R10 skeleton, proven
// 5.8 TB/s). Dropping the split-tf32 correction halves per-k-step issue
// count, freeing the scheduler to keep the LDG stream saturated; occupancy
// raised to 4 CTAs/SM (regs ~50 without the split, no spill risk).
// ---------------------------------------------------------------------------
__global__ __launch_bounds__(256, 4) void maha_kernel(
    const float* __restrict__ x, const float* __restrict__ mean,
    const float* __restrict__ M) {
  const int p = blockIdx.x;
  const int t = threadIdx.x;
  const int wid = t >> 5, lane = t & 31;
  const int tq = lane & 3;    // k-offset within fragment
  const int tr = lane >> 2;   // row/col group index
  __shared__ float sd[CC][NB];   // diff: sd[channel][batch]  (16 KB)
  __shared__ float red[8][NB];

  {
    const float mu = mean[p * CC + t];
    const float* xp = x + (size_t)p * CC + t;
#pragma unroll
    for (int b = 0; b < NB; b++)
      sd[t][b] = xp[(size_t)b * ((size_t)HW * CC)] - mu;
  }
  __syncthreads();

  const float* Mp = M + ((size_t)p << 16);
  const int n0 = wid << 5;

  float c0[4], c1[4], c2[4], c3[4];
#pragma unroll
  for (int nt = 0; nt < 4; nt++) { c0[nt] = c1[nt] = c2[nt] = c3[nt] = 0.f; }

  // load pointer: M[k+tq][n0+tr]; advance 8*CC per k-step
  const float* Ml = Mp + (size_t)tq * CC + n0 + tr;

  float bufA[8], bufB[8];
#pragma unroll
  for (int nt = 0; nt < 4; nt++) {       // k-step 0
    bufA[2 * nt] = Ml[nt * 8];
    bufA[2 * nt + 1] = Ml[nt * 8 + 4 * CC];
  }

#pragma unroll 1
  for (int k0 = 0; k0 < CC; k0 += 16) {
    Ml += 8 * CC;                        // k-step k0+8 (max 248 < 256)
#pragma unroll
    for (int nt = 0; nt < 4; nt++) {
      bufB[2 * nt] = Ml[nt * 8];
      bufB[2 * nt + 1] = Ml[nt * 8 + 4 * CC];
    }
    mma_step(sd, k0, tq, tr, bufA, c0, c1, c2, c3);

    if (k0 + 16 < CC) Ml += 8 * CC;      // k-step k0+16 (tail: harmless reload)
#pragma unroll
    for (int nt = 0; nt < 4; nt++) {
      bufA[2 * nt] = Ml[nt * 8];
      bufA[2 * nt + 1] = Ml[nt * 8 + 4 * CC];
    }
    mma_step(sd, k0 + 8, tq, tr, bufB, c0, c1, c2, c3);
  }

  // ---- epilogue: q[b] += V[b,n] * d[b,n] over this warp's 32 cols ----
  // C frag: c0:(tr, 2tq) c1:(tr, 2tq+1) c2:(tr+8, 2tq) c3:(tr+8, 2tq+1)
  float q0 = 0.f, q1 = 0.f;
#pragma unroll
  for (int nt = 0; nt < 4; nt++) {
    const int n = n0 + nt * 8 + tq * 2;
    q0 += c0[nt] * sd[n][tr]     + c1[nt] * sd[n + 1][tr];
    q1 += c2[nt] * sd[n][tr + 8] + c3[nt] * sd[n + 1][tr + 8];
  }
  q0 += __shfl_xor_sync(0xffffffffu, q0, 1);
  q0 += __shfl_xor_sync(0xffffffffu, q0, 2);
  q1 += __shfl_xor_sync(0xffffffffu, q1, 1);
  q1 += __shfl_xor_sync(0xffffffffu, q1, 2);
  if (tq == 0) {
    red[wid][tr] = q0;
    red[wid][tr + 8] = q1;
  }
  __syncthreads();
  if (t < NB) {
    float s = 0.f;
#pragma unroll
    for (int w = 0; w < 8; w++) s += red[w][t];
    g_mask56[t * HW + p] = sqrtf(fmaxf(s, 0.f));
  }
}

__device__ __forceinline__ int reflect101(int i) {
  if (i < 0) i = -i;
  if (i > 223) i = 446 - i;
  return i;
}

__device__ __forceinline__ void load_weights(float* w, float* inv) {
  const int tid = threadIdx.x;
  if (tid < KS) {
    const float d = (float)(tid - RR);
    w[tid] = expf(-(d * d) / 32.0f);
  }
  __syncthreads();
  if (tid == 0) {
    float s = 0.f;
    for (int j = 0; j < KS; j++) s += w[j];
    *inv = 1.0f / s;
  }
}

// ---------------------------------------------------------------------------
// Kernel 2: FUSED bilinear resize (56->224) + vertical blur; zeroes scores.
// ---------------------------------------------------------------------------
__global__ __launch_bounds__(256) void blur_v_kernel(float* __restrict__ score) {
  __shared__ float s[OH + 32][17];
  __shared__ float w[KS];
  __shared__ float inv;
  load_weights(w, &inv);
  const int tid = threadIdx.x;
  if (blockIdx.x == 0 && tid < NB) score[tid] = 0.0f;
  const int b = blockIdx.x / 14;
  const int xt = (blockIdx.x % 14) * 16;
  const float* mp = g_mask56 + b * HW;
#pragma unroll
  for (int li = tid; li < (OH + 32) * 16; li += 256) {
    const int r = li >> 4, c = li & 15;
    const int gy = reflect101(r - RR);
    const int gx = xt + c;
    const float fy = (gy + 0.5f) * 0.25f - 0.5f;
    const float fx = (gx + 0.5f) * 0.25f - 0.5f;
    const int y0 = (int)floorf(fy);
    const int x0 = (int)floorf(fx);
    const float wy = fy - (float)y0;
    const float wx = fx - (float)x0;
    const int y0c = min(max(y0, 0), 55), y1c = min(max(y0 + 1, 0), 55);
    const int x0c = min(max(x0, 0), 55), x1c = min(max(x0 + 1, 0), 55);
    const float v00 = mp[y0c * 56 + x0c];
    const float v01 = mp[y0c * 56 + x1c];
    const float v10 = mp[y1c * 56 + x0c];
    const float v11 = mp[y1c * 56 + x1c];
    s[r][c] = (1.f - wy) * ((1.f - wx) * v00 + wx * v01) +
              wy * ((1.f - wx) * v10 + wx * v11);
  }
  __syncthreads();
  float* dst = g_tmp + b * OH * OW + xt;
  const int c = tid & 15;
  for (int y = tid >> 4; y < OH; y += 16) {
    float sum = 0.f;
#pragma unroll
    for (int j = 0; j < KS; j++) sum += w[j] * s[y + j][c];
    dst[y * OW + c] = sum * inv;
  }
}

// ---------------------------------------------------------------------------
// Kernel 3: horizontal blur + per-batch max.
// ---------------------------------------------------------------------------
__global__ __launch_bounds__(256) void blur_h_kernel(float* __restrict__ out_mask,
                                                     float* __restrict__ score) {
  __shared__ float s[8][256];
  __shared__ float w[KS];
  __shared__ float inv;
  __shared__ float smx[8];
  load_weights(w, &inv);
  const int tid = threadIdx.x;
  const int b = blockIdx.x / 28;
  const int yt = (blockIdx.x % 28) * 8;
  const float* src = g_tmp + (b * OH + yt) * OW;
#pragma unroll
  for (int li = tid; li < 8 * 256; li += 256) {
    const int r = li >> 8, c = li & 255;
    const int gx = reflect101(c - RR);
    s[r][c] = src[r * OW + gx];
  }
  __syncthreads();
  float* dst = out_mask + (b * OH + yt) * OW;
  const int lane = tid & 31;
  const int r = tid >> 5;
  float mx = 0.f;
#pragma unroll
  for (int x0 = 0; x0 < OW; x0 += 32) {
    const int x = x0 + lane;
    float sum = 0.f;
#pragma unroll
    for (int j = 0; j < KS; j++) sum += w[j] * s[r][x + j];
    sum *= inv;
    dst[r * OW + x] = sum;
    mx = fmaxf(mx, sum);
  }
#pragma unroll
  for (int off = 16; off > 0; off >>= 1)
    mx = fmaxf(mx, __shfl_down_sync(0xffffffffu, mx, off));
  if (lane == 0) smx[r] = mx;
  __syncthreads();
  if (tid == 0) {
    float m2 = smx[0];
#pragma unroll
    for (int k = 1; k < 8; k++) m2 = fmaxf(m2, smx[k]);
    atomicMax((int*)&score[b], __float_as_int(m2));
  }
}

extern "C" void kernel_launch(void* const* d_in, const int* in_sizes, int n_in,
                              void* d_out, int out_size) {
  const float* inputs = (const float*)d_in[0];    // [16,56,56,256]
  const float* mean = (const float*)d_in[1];      // [3136,256]
  const float* cvar_inv = (const float*)d_in[2];  // [3136,256,256]
  float* out = (float*)d_out;
  float* score = out;          // [16,1]
  float* mask = out + NB;      // [16,224,224,1]

  maha_kernel<<<HW, 256>>>(inputs, mean, cvar_inv);
  blur_v_kernel<<<16 * 14, 256>>>(score);
  blur_h_kernel<<<16 * 28, 256>>>(mask, score);
}

// round 13
// speedup vs baseline: 2.0129x; 1.1638x over previous
#include <cuda_runtime.h>
#include <math.h>

#define NB 16
#define HW 3136
#define CC 256
#define OH 224
#define OW 224
#define RR 16
#define KS 33
#define NOUT (NB*OH*OW)

__device__ float g_mask56[NB * HW];
__device__ float g_tmp[NOUT];

// ---------------------------------------------------------------------------
// Padded triangular job schedule (per warp): 4 segments, one per owned n-tile
// j = {w, 15-w, 16+w, 31-w}; segment slots padded to {8,16,24,32} (sum 80,
// real jobs 66). Slot g -> (kt, j); dummy slots clamp kt to j (L1 hit reload).
// ---------------------------------------------------------------------------
__device__ __forceinline__ const float* job_ptr(
    const float* Mp, int gg, int w, int tq, int tr) {
  gg = min(gg, 79);
  int kt, j;
  if (gg < 8)       { kt = gg;      j = w; }
  else if (gg < 24) { kt = gg - 8;  j = 15 - w; }
  else if (gg < 48) { kt = gg - 24; j = 16 + w; }
  else              { kt = gg - 48; j = 31 - w; }
  kt = min(kt, j);
  return Mp + (size_t)((kt * 8 + tq) * CC + j * 8 + tr);
}

template <int NT>
__device__ __forceinline__ void seg_mma(
    const uint4 a, unsigned bh0, unsigned bh1,
    float* c0, float* c1, float* c2, float* c3) {
  asm("mma.sync.aligned.m16n8k8.row.col.f32.tf32.tf32.f32 "
      "{%0,%1,%2,%3}, {%4,%5,%6,%7}, {%8,%9}, {%0,%1,%2,%3};"
      : "+f"(c0[NT]), "+f"(c1[NT]), "+f"(c2[NT]), "+f"(c3[NT])
      : "r"(a.x), "r"(a.y), "r"(a.z), "r"(a.w), "r"(bh0), "r"(bh1));
}

// One segment: fixed n-tile (compile-time accumulator index NT), kt = slot.
// Every slot: mask B (1 / 0.5 / 0 triangular weight), cvt, prefetch slot+4
// (cross-segment via job_ptr), LDS.128 A fragment (pre-cvt tf32), 1 MMA.
template <int NT, int SEGLEN>
__device__ __forceinline__ void run_segment(
    const float* Mp, const uint4* sdA, int segbase, int j, int w,
    int tq, int tr, int lane, float* r0, float* r1,
    float* c0, float* c1, float* c2, float* c3) {
#pragma unroll 1
  for (int it = 0; it < SEGLEN / 4; it++) {
#pragma unroll
    for (int u = 0; u < 4; u++) {
      const int kt = it * 4 + u;
      float b0 = r0[u], b1 = r1[u];
      const float w0 = (kt < j) ? 1.f : (kt > j) ? 0.f
                       : ((tq < tr) ? 1.f : (tq == tr) ? 0.5f : 0.f);
      const float w1 = (kt < j) ? 1.f : (kt > j) ? 0.f
                       : ((tq + 4 < tr) ? 1.f : (tq + 4 == tr) ? 0.5f : 0.f);
      b0 *= w0;
      b1 *= w1;
      unsigned bh0, bh1;
      asm("cvt.rna.tf32.f32 %0, %1;" : "=r"(bh0) : "f"(b0));
      asm("cvt.rna.tf32.f32 %0, %1;" : "=r"(bh1) : "f"(b1));
      const float* np = job_ptr(Mp, segbase + kt + 4, w, tq, tr);
      r0[u] = np[0];
      r1[u] = np[4 * CC];
      const uint4 a = sdA[kt * 32 + lane];
      seg_mma<NT>(a, bh0, bh1, c0, c1, c2, c3);
    }
  }
}

// ---------------------------------------------------------------------------
// Kernel 1: per-pixel Mahalanobis via tensor cores + symmetry, slot-uniform
// triangular schedule. Reads only upper-triangle tiles (51.6% of 822 MB);
// every slot issues exactly 2 LDGs with a 4-deep ring (8 in flight), so the
// MLP that gave R10/R11 6 TB/s is preserved. A fragments pre-staged in SMEM
// (tf32, fragment order) -> one conflict-free LDS.128 per job.
// quad = 2 * sum (diagonal elements at weight 1/2).
// ---------------------------------------------------------------------------
__global__ __launch_bounds__(256, 4) void maha_kernel(
    const float* __restrict__ x, const float* __restrict__ mean,
    const float* __restrict__ M) {
  const int p = blockIdx.x;
  const int t = threadIdx.x;
  const int wid = t >> 5, lane = t & 31;
  const int tq = lane & 3;    // k-offset within fragment
  const int tr = lane >> 2;   // row/col group index
  __shared__ float sd[CC][NB];      // diff: sd[channel][batch]   (16 KB)
  __shared__ uint4 sdA[32 * 32];    // A fragments, tf32, frag order (16 KB)
  __shared__ float red[8][NB];

  {
    const float mu = mean[p * CC + t];
    const float* xp = x + (size_t)p * CC + t;
#pragma unroll
    for (int b = 0; b < NB; b++)
      sd[t][b] = xp[(size_t)b * ((size_t)HW * CC)] - mu;
  }
  __syncthreads();

  // stage all 32 A fragments (pre-converted to tf32)
#pragma unroll
  for (int s2 = 0; s2 < 4; s2++) {
    const int kt = wid + s2 * 8;
    unsigned x0, x1, x2, x3;
    asm("cvt.rna.tf32.f32 %0, %1;" : "=r"(x0) : "f"(sd[kt * 8 + tq][tr]));
    asm("cvt.rna.tf32.f32 %0, %1;" : "=r"(x1) : "f"(sd[kt * 8 + tq][tr + 8]));
    asm("cvt.rna.tf32.f32 %0, %1;" : "=r"(x2) : "f"(sd[kt * 8 + tq + 4][tr]));
    asm("cvt.rna.tf32.f32 %0, %1;" : "=r"(x3) : "f"(sd[kt * 8 + tq + 4][tr + 8]));
    sdA[kt * 32 + lane] = make_uint4(x0, x1, x2, x3);
  }
  __syncthreads();

  const float* Mp = M + ((size_t)p << 16);
  const int w = wid;

  float c0[4], c1[4], c2[4], c3[4];
#pragma unroll
  for (int nt = 0; nt < 4; nt++) { c0[nt] = c1[nt] = c2[nt] = c3[nt] = 0.f; }

  // prologue: ring slots 0..3
  float r0[4], r1[4];
#pragma unroll
  for (int u = 0; u < 4; u++) {
    const float* ptr = job_ptr(Mp, u, w, tq, tr);
    r0[u] = ptr[0];
    r1[u] = ptr[4 * CC];
  }

  run_segment<0, 8>(Mp, sdA, 0, w, w, tq, tr, lane, r0, r1, c0, c1, c2, c3);
  run_segment<1, 16>(Mp, sdA, 8, 15 - w, w, tq, tr, lane, r0, r1, c0, c1, c2, c3);
  run_segment<2, 24>(Mp, sdA, 24, 16 + w, w, tq, tr, lane, r0, r1, c0, c1, c2, c3);
  run_segment<3, 32>(Mp, sdA, 48, 31 - w, w, tq, tr, lane, r0, r1, c0, c1, c2, c3);

  // ---- epilogue: q[b] += V[b,n] * d[b,n]; quad = 2 * total ----
  // C frag: c0:(tr, 2tq) c1:(tr, 2tq+1) c2:(tr+8, 2tq) c3:(tr+8, 2tq+1)
  const int jl[4] = {w, 15 - w, 16 + w, 31 - w};
  float q0 = 0.f, q1 = 0.f;
#pragma unroll
  for (int nt = 0; nt < 4; nt++) {
    const int n = jl[nt] * 8 + tq * 2;
    q0 += c0[nt] * sd[n][tr]     + c1[nt] * sd[n + 1][tr];
    q1 += c2[nt] * sd[n][tr + 8] + c3[nt] * sd[n + 1][tr + 8];
  }
  q0 += __shfl_xor_sync(0xffffffffu, q0, 1);
  q0 += __shfl_xor_sync(0xffffffffu, q0, 2);
  q1 += __shfl_xor_sync(0xffffffffu, q1, 1);
  q1 += __shfl_xor_sync(0xffffffffu, q1, 2);
  if (tq == 0) {
    red[wid][tr] = q0;
    red[wid][tr + 8] = q1;
  }
  __syncthreads();
  if (t < NB) {
    float s = 0.f;
#pragma unroll
    for (int ww = 0; ww < 8; ww++) s += red[ww][t];
    g_mask56[t * HW + p] = sqrtf(fmaxf(2.0f * s, 0.f));
  }
}

__device__ __forceinline__ int reflect101(int i) {
  if (i < 0) i = -i;
  if (i > 223) i = 446 - i;
  return i;
}

__device__ __forceinline__ void load_weights(float* w, float* inv) {
  const int tid = threadIdx.x;
  if (tid < KS) {
    const float d = (float)(tid - RR);
    w[tid] = expf(-(d * d) / 32.0f);
  }
  __syncthreads();
  if (tid == 0) {
    float s = 0.f;
    for (int j = 0; j < KS; j++) s += w[j];
    *inv = 1.0f / s;
  }
}

// ---------------------------------------------------------------------------
// Kernel 2: FUSED bilinear resize (56->224) + vertical blur; zeroes scores.
// ---------------------------------------------------------------------------
__global__ __launch_bounds__(256) void blur_v_kernel(float* __restrict__ score) {
  __shared__ float s[OH + 32][17];
  __shared__ float w[KS];
  __shared__ float inv;
  load_weights(w, &inv);
  const int tid = threadIdx.x;
  if (blockIdx.x == 0 && tid < NB) score[tid] = 0.0f;
  const int b = blockIdx.x / 14;
  const int xt = (blockIdx.x % 14) * 16;
  const float* mp = g_mask56 + b * HW;
#pragma unroll
  for (int li = tid; li < (OH + 32) * 16; li += 256) {
    const int r = li >> 4, c = li & 15;
    const int gy = reflect101(r - RR);
    const int gx = xt + c;
    const float fy = (gy + 0.5f) * 0.25f - 0.5f;
    const float fx = (gx + 0.5f) * 0.25f - 0.5f;
    const int y0 = (int)floorf(fy);
    const int x0 = (int)floorf(fx);
    const float wy = fy - (float)y0;
    const float wx = fx - (float)x0;
    const int y0c = min(max(y0, 0), 55), y1c = min(max(y0 + 1, 0), 55);
    const int x0c = min(max(x0, 0), 55), x1c = min(max(x0 + 1, 0), 55);
    const float v00 = mp[y0c * 56 + x0c];
    const float v01 = mp[y0c * 56 + x1c];
    const float v10 = mp[y1c * 56 + x0c];
    const float v11 = mp[y1c * 56 + x1c];
    s[r][c] = (1.f - wy) * ((1.f - wx) * v00 + wx * v01) +
              wy * ((1.f - wx) * v10 + wx * v11);
  }
  __syncthreads();
  float* dst = g_tmp + b * OH * OW + xt;
  const int c = tid & 15;
  for (int y = tid >> 4; y < OH; y += 16) {
    float sum = 0.f;
#pragma unroll
    for (int j = 0; j < KS; j++) sum += w[j] * s[y + j][c];
    dst[y * OW + c] = sum * inv;
  }
}

// ---------------------------------------------------------------------------
// Kernel 3: horizontal blur + per-batch max.
// ---------------------------------------------------------------------------
__global__ __launch_bounds__(256) void blur_h_kernel(float* __restrict__ out_mask,
                                                     float* __restrict__ score) {
  __shared__ float s[8][256];
  __shared__ float w[KS];
  __shared__ float inv;
  __shared__ float smx[8];
  load_weights(w, &inv);
  const int tid = threadIdx.x;
  const int b = blockIdx.x / 28;
  const int yt = (blockIdx.x % 28) * 8;
  const float* src = g_tmp + (b * OH + yt) * OW;
#pragma unroll
  for (int li = tid; li < 8 * 256; li += 256) {
    const int r = li >> 8, c = li & 255;
    const int gx = reflect101(c - RR);
    s[r][c] = src[r * OW + gx];
  }
  __syncthreads();
  float* dst = out_mask + (b * OH + yt) * OW;
  const int lane = tid & 31;
  const int r = tid >> 5;
  float mx = 0.f;
#pragma unroll
  for (int x0 = 0; x0 < OW; x0 += 32) {
    const int x = x0 + lane;
    float sum = 0.f;
#pragma unroll
    for (int j = 0; j < KS; j++) sum += w[j] * s[r][x + j];
    sum *= inv;
    dst[r * OW + x] = sum;
    mx = fmaxf(mx, sum);
  }
#pragma unroll
  for (int off = 16; off > 0; off >>= 1)
    mx = fmaxf(mx, __shfl_down_sync(0xffffffffu, mx, off));
  if (lane == 0) smx[r] = mx;
  __syncthreads();
  if (tid == 0) {
    float m2 = smx[0];
#pragma unroll
    for (int k = 1; k < 8; k++) m2 = fmaxf(m2, smx[k]);
    atomicMax((int*)&score[b], __float_as_int(m2));
  }
}

extern "C" void kernel_launch(void* const* d_in, const int* in_sizes, int n_in,
                              void* d_out, int out_size) {
  const float* inputs = (const float*)d_in[0];    // [16,56,56,256]
  const float* mean = (const float*)d_in[1];      // [3136,256]
  const float* cvar_inv = (const float*)d_in[2];  // [3136,256,256]
  float* out = (float*)d_out;
  float* score = out;          // [16,1]
  float* mask = out + NB;      // [16,224,224,1]

  maha_kernel<<<HW, 256>>>(inputs, mean, cvar_inv);
  blur_v_kernel<<<16 * 14, 256>>>(score);
  blur_h_kernel<<<16 * 28, 256>>>(mask, score);
}

// round 14
// speedup vs baseline: 2.0718x; 1.0293x over previous
#include <cuda_runtime.h>
#include <math.h>

#define NB 16
#define HW 3136
#define CC 256
#define OH 224
#define OW 224
#define RR 16
#define KS 33
#define NOUT (NB*OH*OW)

__device__ float g_mask56[NB * HW];
__device__ float g_tmp[NOUT];

// ---------------------------------------------------------------------------
// One fully-unrolled segment of the padded triangular schedule.
// Segment = n-tile j (runtime, warp-dependent), slots kt = 0..SEGLEN-1
// (compile-time after unroll). Every slot: mask B by triangular weight
// (1 if kt<j, dw if kt==j, 0 if kt>j; dw hoisted), cvt, prefetch slot kt+4
// (same segment or next segment base -> compile-time immediate offsets,
// zero ALU), LDS.128 A fragment, 1 MMA. Ring lane kt&3 is compile-time.
// ---------------------------------------------------------------------------
template <int NT, int SEGLEN>
__device__ __forceinline__ void run_segment(
    const float* seg_base, const float* next_base, const uint4* sdA,
    int j, float dw0, float dw1, int lane,
    float* r0, float* r1, float* c0, float* c1, float* c2, float* c3) {
#pragma unroll
  for (int kt = 0; kt < SEGLEN; kt++) {
    const int u = kt & 3;
    float b0 = r0[u], b1 = r1[u];
    // prefetch slot kt+4 (compile-time base select + immediate offset)
    const float* np = (kt + 4 < SEGLEN)
                          ? (seg_base + (kt + 4) * (8 * CC))
                          : (next_base + (kt + 4 - SEGLEN) * (8 * CC));
    r0[u] = np[0];
    r1[u] = np[4 * CC];
    // triangular weight (j runtime; kt compile-time)
    const float s0 = (kt < j) ? 1.f : ((kt == j) ? dw0 : 0.f);
    const float s1 = (kt < j) ? 1.f : ((kt == j) ? dw1 : 0.f);
    b0 *= s0;
    b1 *= s1;
    unsigned bh0, bh1;
    asm("cvt.rna.tf32.f32 %0, %1;" : "=r"(bh0) : "f"(b0));
    asm("cvt.rna.tf32.f32 %0, %1;" : "=r"(bh1) : "f"(b1));
    const uint4 a = sdA[kt * 32 + lane];
    asm("mma.sync.aligned.m16n8k8.row.col.f32.tf32.tf32.f32 "
        "{%0,%1,%2,%3}, {%4,%5,%6,%7}, {%8,%9}, {%0,%1,%2,%3};"
        : "+f"(c0[NT]), "+f"(c1[NT]), "+f"(c2[NT]), "+f"(c3[NT])
        : "r"(a.x), "r"(a.y), "r"(a.z), "r"(a.w), "r"(bh0), "r"(bh1));
  }
}

// ---------------------------------------------------------------------------
// Kernel 1: per-pixel Mahalanobis via tensor cores + symmetry, slot-uniform
// padded triangular schedule (R13 winner), with all 80 slots fully unrolled:
// addressing is pure immediate offsets, masks hoisted -> per-slot issue cost
// ~15 instrs (was ~24). quad = 2 * sum (diagonal at weight 1/2).
// ---------------------------------------------------------------------------
__global__ __launch_bounds__(256, 4) void maha_kernel(
    const float* __restrict__ x, const float* __restrict__ mean,
    const float* __restrict__ M) {
  const int p = blockIdx.x;
  const int t = threadIdx.x;
  const int wid = t >> 5, lane = t & 31;
  const int tq = lane & 3;    // k-offset within fragment
  const int tr = lane >> 2;   // row/col group index
  __shared__ float sd[CC][NB];      // diff: sd[channel][batch]   (16 KB)
  __shared__ uint4 sdA[32 * 32];    // A fragments, tf32, frag order (16 KB)
  __shared__ float red[8][NB];

  {
    const float mu = mean[p * CC + t];
    const float* xp = x + (size_t)p * CC + t;
#pragma unroll
    for (int b = 0; b < NB; b++)
      sd[t][b] = xp[(size_t)b * ((size_t)HW * CC)] - mu;
  }
  __syncthreads();

  // stage all 32 A fragments (pre-converted to tf32)
#pragma unroll
  for (int s2 = 0; s2 < 4; s2++) {
    const int kt = wid + s2 * 8;
    unsigned x0, x1, x2, x3;
    asm("cvt.rna.tf32.f32 %0, %1;" : "=r"(x0) : "f"(sd[kt * 8 + tq][tr]));
    asm("cvt.rna.tf32.f32 %0, %1;" : "=r"(x1) : "f"(sd[kt * 8 + tq][tr + 8]));
    asm("cvt.rna.tf32.f32 %0, %1;" : "=r"(x2) : "f"(sd[kt * 8 + tq + 4][tr]));
    asm("cvt.rna.tf32.f32 %0, %1;" : "=r"(x3) : "f"(sd[kt * 8 + tq + 4][tr + 8]));
    sdA[kt * 32 + lane] = make_uint4(x0, x1, x2, x3);
  }
  __syncthreads();

  const float* Mp = M + ((size_t)p << 16);
  const int w = wid;

  // diagonal-tile lane weights (kt-invariant, hoisted)
  const float dw0 = (tq < tr) ? 1.f : (tq == tr) ? 0.5f : 0.f;
  const float dw1 = (tq + 4 < tr) ? 1.f : (tq + 4 == tr) ? 0.5f : 0.f;

  // segment base pointers: base(j) = Mp + tq*CC + j*8 + tr
  const float* tb = Mp + tq * CC + tr;
  const float* sb0 = tb + w * 8;
  const float* sb1 = tb + (15 - w) * 8;
  const float* sb2 = tb + (16 + w) * 8;
  const float* sb3 = tb + (31 - w) * 8;

  float c0[4], c1[4], c2[4], c3[4];
#pragma unroll
  for (int nt = 0; nt < 4; nt++) { c0[nt] = c1[nt] = c2[nt] = c3[nt] = 0.f; }

  // prologue: ring slots 0..3 (segment 0, kt = 0..3; kt>j harmless, masked)
  float r0[4], r1[4];
#pragma unroll
  for (int u = 0; u < 4; u++) {
    const float* ptr = sb0 + u * (8 * CC);
    r0[u] = ptr[0];
    r1[u] = ptr[4 * CC];
  }

  run_segment<0, 8>(sb0, sb1, sdA, w, dw0, dw1, lane, r0, r1, c0, c1, c2, c3);
  run_segment<1, 16>(sb1, sb2, sdA, 15 - w, dw0, dw1, lane, r0, r1, c0, c1, c2, c3);
  run_segment<2, 24>(sb2, sb3, sdA, 16 + w, dw0, dw1, lane, r0, r1, c0, c1, c2, c3);
  run_segment<3, 32>(sb3, sb3, sdA, 31 - w, dw0, dw1, lane, r0, r1, c0, c1, c2, c3);

  // ---- epilogue: q[b] += V[b,n] * d[b,n]; quad = 2 * total ----
  // C frag: c0:(tr, 2tq) c1:(tr, 2tq+1) c2:(tr+8, 2tq) c3:(tr+8, 2tq+1)
  const int jl[4] = {w, 15 - w, 16 + w, 31 - w};
  float q0 = 0.f, q1 = 0.f;
#pragma unroll
  for (int nt = 0; nt < 4; nt++) {
    const int n = jl[nt] * 8 + tq * 2;
    q0 += c0[nt] * sd[n][tr]     + c1[nt] * sd[n + 1][tr];
    q1 += c2[nt] * sd[n][tr + 8] + c3[nt] * sd[n + 1][tr + 8];
  }
  q0 += __shfl_xor_sync(0xffffffffu, q0, 1);
  q0 += __shfl_xor_sync(0xffffffffu, q0, 2);
  q1 += __shfl_xor_sync(0xffffffffu, q1, 1);
  q1 += __shfl_xor_sync(0xffffffffu, q1, 2);
  if (tq == 0) {
    red[wid][tr] = q0;
    red[wid][tr + 8] = q1;
  }
  __syncthreads();
  if (t < NB) {
    float s = 0.f;
#pragma unroll
    for (int ww = 0; ww < 8; ww++) s += red[ww][t];
    g_mask56[t * HW + p] = sqrtf(fmaxf(2.0f * s, 0.f));
  }
}

__device__ __forceinline__ int reflect101(int i) {
  if (i < 0) i = -i;
  if (i > 223) i = 446 - i;
  return i;
}

__device__ __forceinline__ void load_weights(float* w, float* inv) {
  const int tid = threadIdx.x;
  if (tid < KS) {
    const float d = (float)(tid - RR);
    w[tid] = expf(-(d * d) / 32.0f);
  }
  __syncthreads();
  if (tid == 0) {
    float s = 0.f;
    for (int j = 0; j < KS; j++) s += w[j];
    *inv = 1.0f / s;
  }
}

// ---------------------------------------------------------------------------
// Kernel 2: FUSED bilinear resize (56->224) + vertical blur; zeroes scores.
// ---------------------------------------------------------------------------
__global__ __launch_bounds__(256) void blur_v_kernel(float* __restrict__ score) {
  __shared__ float s[OH + 32][17];
  __shared__ float w[KS];
  __shared__ float inv;
  load_weights(w, &inv);
  const int tid = threadIdx.x;
  if (blockIdx.x == 0 && tid < NB) score[tid] = 0.0f;
  const int b = blockIdx.x / 14;
  const int xt = (blockIdx.x % 14) * 16;
  const float* mp = g_mask56 + b * HW;
#pragma unroll
  for (int li = tid; li < (OH + 32) * 16; li += 256) {
    const int r = li >> 4, c = li & 15;
    const int gy = reflect101(r - RR);
    const int gx = xt + c;
    const float fy = (gy + 0.5f) * 0.25f - 0.5f;
    const float fx = (gx + 0.5f) * 0.25f - 0.5f;
    const int y0 = (int)floorf(fy);
    const int x0 = (int)floorf(fx);
    const float wy = fy - (float)y0;
    const float wx = fx - (float)x0;
    const int y0c = min(max(y0, 0), 55), y1c = min(max(y0 + 1, 0), 55);
    const int x0c = min(max(x0, 0), 55), x1c = min(max(x0 + 1, 0), 55);
    const float v00 = mp[y0c * 56 + x0c];
    const float v01 = mp[y0c * 56 + x1c];
    const float v10 = mp[y1c * 56 + x0c];
    const float v11 = mp[y1c * 56 + x1c];
    s[r][c] = (1.f - wy) * ((1.f - wx) * v00 + wx * v01) +
              wy * ((1.f - wx) * v10 + wx * v11);
  }
  __syncthreads();
  float* dst = g_tmp + b * OH * OW + xt;
  const int c = tid & 15;
  for (int y = tid >> 4; y < OH; y += 16) {
    float sum = 0.f;
#pragma unroll
    for (int j = 0; j < KS; j++) sum += w[j] * s[y + j][c];
    dst[y * OW + c] = sum * inv;
  }
}

// ---------------------------------------------------------------------------
// Kernel 3: horizontal blur + per-batch max.
// ---------------------------------------------------------------------------
__global__ __launch_bounds__(256) void blur_h_kernel(float* __restrict__ out_mask,
                                                     float* __restrict__ score) {
  __shared__ float s[8][256];
  __shared__ float w[KS];
  __shared__ float inv;
  __shared__ float smx[8];
  load_weights(w, &inv);
  const int tid = threadIdx.x;
  const int b = blockIdx.x / 28;
  const int yt = (blockIdx.x % 28) * 8;
  const float* src = g_tmp + (b * OH + yt) * OW;
#pragma unroll
  for (int li = tid; li < 8 * 256; li += 256) {
    const int r = li >> 8, c = li & 255;
    const int gx = reflect101(c - RR);
    s[r][c] = src[r * OW + gx];
  }
  __syncthreads();
  float* dst = out_mask + (b * OH + yt) * OW;
  const int lane = tid & 31;
  const int r = tid >> 5;
  float mx = 0.f;
#pragma unroll
  for (int x0 = 0; x0 < OW; x0 += 32) {
    const int x = x0 + lane;
    float sum = 0.f;
#pragma unroll
    for (int j = 0; j < KS; j++) sum += w[j] * s[r][x + j];
    sum *= inv;
    dst[r * OW + x] = sum;
    mx = fmaxf(mx, sum);
  }
#pragma unroll
  for (int off = 16; off > 0; off >>= 1)
    mx = fmaxf(mx, __shfl_down_sync(0xffffffffu, mx, off));
  if (lane == 0) smx[r] = mx;
  __syncthreads();
  if (tid == 0) {
    float m2 = smx[0];
#pragma unroll
    for (int k = 1; k < 8; k++) m2 = fmaxf(m2, smx[k]);
    atomicMax((int*)&score[b], __float_as_int(m2));
  }
}

extern "C" void kernel_launch(void* const* d_in, const int* in_sizes, int n_in,
                              void* d_out, int out_size) {
  const float* inputs = (const float*)d_in[0];    // [16,56,56,256]
  const float* mean = (const float*)d_in[1];      // [3136,256]
  const float* cvar_inv = (const float*)d_in[2];  // [3136,256,256]
  float* out = (float*)d_out;
  float* score = out;          // [16,1]
  float* mask = out + NB;      // [16,224,224,1]

  maha_kernel<<<HW, 256>>>(inputs, mean, cvar_inv);
  blur_v_kernel<<<16 * 14, 256>>>(score);
  blur_h_kernel<<<16 * 28, 256>>>(mask, score);
}